// round 1
// baseline (speedup 1.0000x reference)
#include <cuda_runtime.h>
#include <math.h>

typedef unsigned int u32;
typedef unsigned long long u64;

#define NLEV 16
#define HSIZE (1u << 19)
#define HMASK (HSIZE - 1u)
#define NPTS (4096 * 128)

struct Consts { float res[NLEV]; };

// scratch: per-point log-density for the volume-rendering pass
__device__ __align__(16) float g_logd[NPTS];

// ---------- packed f32x2 helpers ----------
__device__ __forceinline__ u64 pk2(float a, float b) {
    u64 r; asm("mov.b64 %0,{%1,%2};" : "=l"(r) : "f"(a), "f"(b)); return r;
}
__device__ __forceinline__ void up2(u64 v, float& a, float& b) {
    asm("mov.b64 {%0,%1},%2;" : "=f"(a), "=f"(b) : "l"(v));
}
__device__ __forceinline__ u64 f2fma(u64 a, u64 b, u64 c) {
    u64 d; asm("fma.rn.f32x2 %0,%1,%2,%3;" : "=l"(d) : "l"(a), "l"(b), "l"(c)); return d;
}

struct __align__(16) SW {
    float win[32 * 64];   // 2048
    float wout[64 * 16];  // 1024
    float w1[15 * 64];    // 960
    float w2[64 * 64];    // 4096
    float w3[64 * 3];     // 192
};

__global__ void __launch_bounds__(128, 3) fused_point_kernel(
    const float* __restrict__ xyz, const float* __restrict__ table,
    const float* __restrict__ w_in, const float* __restrict__ w_out,
    const float* __restrict__ rw1, const float* __restrict__ rw2,
    const float* __restrict__ rw3, float* __restrict__ out, Consts cc)
{
    __shared__ SW sm;
    const int t = threadIdx.x;
    for (int i = t; i < 2048; i += 128) sm.win[i]  = w_in[i];
    for (int i = t; i < 1024; i += 128) sm.wout[i] = w_out[i];
    for (int i = t; i < 960;  i += 128) sm.w1[i]   = rw1[i];
    for (int i = t; i < 4096; i += 128) sm.w2[i]   = rw2[i];
    for (int i = t; i < 192;  i += 128) sm.w3[i]   = rw3[i];
    __syncthreads();

    const int p = blockIdx.x * 128 + t;
    const float px = __ldg(xyz + 3 * p);
    const float py = __ldg(xyz + 3 * p + 1);
    const float pz = __ldg(xyz + 3 * p + 2);

    // ---- hash-grid encode fused with layer 1 (enc @ w_in) ----
    u64 hA[32];
    #pragma unroll
    for (int j = 0; j < 32; j++) hA[j] = 0ULL;

    #pragma unroll 2
    for (int l = 0; l < NLEV; l++) {
        const float r = cc.res[l];
        const float X = px * r, Y = py * r, Z = pz * r;
        const float fx = floorf(X), fy = floorf(Y), fz = floorf(Z);
        const float ax = X - fx, ay = Y - fy, az = Z - fz;
        const u32 ix = (u32)fx, iy = (u32)fy, iz = (u32)fz;
        const u32 hx0 = ix, hx1 = ix + 1u;
        const u32 hy0 = iy * 2654435761u, hy1 = hy0 + 2654435761u;
        const u32 hz0 = iz * 805459861u,  hz1 = hz0 + 805459861u;
        const float2* tab = (const float2*)table + (size_t)l * HSIZE;
        const float bx = 1.f - ax, by = 1.f - ay, bz = 1.f - az;

        float a0 = 0.f, a1 = 0.f;
        #pragma unroll
        for (int c = 0; c < 8; c++) {
            const u32 hx = (c & 4) ? hx1 : hx0;
            const u32 hy = (c & 2) ? hy1 : hy0;
            const u32 hz = (c & 1) ? hz1 : hz0;
            const u32 idx = (hx ^ hy ^ hz) & HMASK;
            const float2 tv = __ldg(tab + idx);
            const float w = ((c & 4) ? ax : bx) * ((c & 2) ? ay : by) * ((c & 1) ? az : bz);
            a0 = fmaf(w, tv.x, a0);
            a1 = fmaf(w, tv.y, a1);
        }
        // accumulate enc[2l], enc[2l+1] into hidden (rows 2l, 2l+1 of w_in)
        const u64 e0 = pk2(a0, a0), e1 = pk2(a1, a1);
        const u64* r0 = (const u64*)(sm.win + (2 * l) * 64);
        const u64* r1 = r0 + 32;
        #pragma unroll
        for (int j = 0; j < 32; j += 2) {
            const ulonglong2 wv0 = *(const ulonglong2*)(r0 + j);
            const ulonglong2 wv1 = *(const ulonglong2*)(r1 + j);
            hA[j]     = f2fma(e1, wv1.x, f2fma(e0, wv0.x, hA[j]));
            hA[j + 1] = f2fma(e1, wv1.y, f2fma(e0, wv0.y, hA[j + 1]));
        }
    }

    // ---- layer 2: raw = relu(h) @ w_out  (16 outputs) ----
    u64 raw2[8];
    #pragma unroll
    for (int j = 0; j < 8; j++) raw2[j] = 0ULL;
    #pragma unroll
    for (int ic = 0; ic < 32; ic++) {
        float v0, v1; up2(hA[ic], v0, v1);
        v0 = fmaxf(v0, 0.f); v1 = fmaxf(v1, 0.f);
        const u64 e0 = pk2(v0, v0), e1 = pk2(v1, v1);
        const u64* r0 = (const u64*)(sm.wout + (2 * ic) * 16);
        const u64* r1 = r0 + 8;
        #pragma unroll
        for (int j = 0; j < 8; j += 2) {
            const ulonglong2 wv0 = *(const ulonglong2*)(r0 + j);
            const ulonglong2 wv1 = *(const ulonglong2*)(r1 + j);
            raw2[j]     = f2fma(e1, wv1.x, f2fma(e0, wv0.x, raw2[j]));
            raw2[j + 1] = f2fma(e1, wv1.y, f2fma(e0, wv0.y, raw2[j + 1]));
        }
    }
    float raw[16];
    #pragma unroll
    for (int j = 0; j < 8; j++) up2(raw2[j], raw[2 * j], raw[2 * j + 1]);
    g_logd[p] = raw[0];

    // ---- rgb layer 1: h1 = relu(feats @ rgb_w1), feats = raw[1..15] ----
    #pragma unroll
    for (int j = 0; j < 32; j++) hA[j] = 0ULL;
    #pragma unroll
    for (int i = 0; i < 15; i++) {
        const u64 e = pk2(raw[i + 1], raw[i + 1]);
        const u64* row = (const u64*)(sm.w1 + i * 64);
        #pragma unroll
        for (int j = 0; j < 32; j += 2) {
            const ulonglong2 wv = *(const ulonglong2*)(row + j);
            hA[j]     = f2fma(e, wv.x, hA[j]);
            hA[j + 1] = f2fma(e, wv.y, hA[j + 1]);
        }
    }

    // ---- rgb layer 2: h2 = relu(h1) @ rgb_w2 ----
    u64 hB[32];
    #pragma unroll
    for (int j = 0; j < 32; j++) hB[j] = 0ULL;
    #pragma unroll
    for (int ic = 0; ic < 32; ic++) {
        float v0, v1; up2(hA[ic], v0, v1);
        v0 = fmaxf(v0, 0.f); v1 = fmaxf(v1, 0.f);
        const u64 e0 = pk2(v0, v0), e1 = pk2(v1, v1);
        const u64* r0 = (const u64*)(sm.w2 + (2 * ic) * 64);
        const u64* r1 = r0 + 32;
        #pragma unroll
        for (int j = 0; j < 32; j += 2) {
            const ulonglong2 wv0 = *(const ulonglong2*)(r0 + j);
            const ulonglong2 wv1 = *(const ulonglong2*)(r1 + j);
            hB[j]     = f2fma(e1, wv1.x, f2fma(e0, wv0.x, hB[j]));
            hB[j + 1] = f2fma(e1, wv1.y, f2fma(e0, wv0.y, hB[j + 1]));
        }
    }

    // ---- rgb out: sigmoid(relu(h2) @ rgb_w3) ----
    float cr = 0.f, cg = 0.f, cb = 0.f;
    #pragma unroll
    for (int ic = 0; ic < 32; ic++) {
        float v0, v1; up2(hB[ic], v0, v1);
        v0 = fmaxf(v0, 0.f); v1 = fmaxf(v1, 0.f);
        const float* q = sm.w3 + (2 * ic) * 3;
        cr = fmaf(v0, q[0], fmaf(v1, q[3], cr));
        cg = fmaf(v0, q[1], fmaf(v1, q[4], cg));
        cb = fmaf(v0, q[2], fmaf(v1, q[5], cb));
    }
    out[4 * p + 1] = 1.f / (1.f + expf(-cr));
    out[4 * p + 2] = 1.f / (1.f + expf(-cg));
    out[4 * p + 3] = 1.f / (1.f + expf(-cb));
}

// ---- volume-rendering weights: one warp per ray, S=128 samples ----
__global__ void __launch_bounds__(128) volrend_kernel(
    const float* __restrict__ delta, float* __restrict__ out, float offset)
{
    const int warp = (blockIdx.x * 128 + threadIdx.x) >> 5;  // ray id, 0..4095
    const int lane = threadIdx.x & 31;
    const int base = warp * 128;

    const float4 ld = *((const float4*)(g_logd + base) + lane);
    const float4 dt = *((const float4*)(delta + base) + lane);

    const float d0 = expf(ld.x + offset + logf(dt.x));
    const float d1 = expf(ld.y + offset + logf(dt.y));
    const float d2 = expf(ld.z + offset + logf(dt.z));
    const float d3 = expf(ld.w + offset + logf(dt.w));

    const float p0 = d0, p1 = p0 + d1, p2 = p1 + d2, p3 = p2 + d3;

    // warp-inclusive scan of per-lane sums
    float s = p3;
    #pragma unroll
    for (int o = 1; o < 32; o <<= 1) {
        const float v = __shfl_up_sync(0xffffffffu, s, o);
        if (lane >= o) s += v;
    }
    const float excl = s - p3;

    const float w0 = (1.f - expf(-d0)) * expf(-excl);
    const float w1 = (1.f - expf(-d1)) * expf(-(excl + p0));
    const float w2 = (1.f - expf(-d2)) * expf(-(excl + p1));
    const float w3 = (1.f - expf(-d3)) * expf(-(excl + p2));

    const int s0 = base + lane * 4;
    out[(s0 + 0) * 4] = w0;
    out[(s0 + 1) * 4] = w1;
    out[(s0 + 2) * 4] = w2;
    out[(s0 + 3) * 4] = w3;
}

extern "C" void kernel_launch(void* const* d_in, const int* in_sizes, int n_in,
                              void* d_out, int out_size)
{
    const float* xyz   = (const float*)d_in[0];
    const float* delta = (const float*)d_in[1];
    const float* table = (const float*)d_in[2];
    const float* w_in  = (const float*)d_in[3];
    const float* w_out = (const float*)d_in[4];
    const float* rw1   = (const float*)d_in[5];
    const float* rw2   = (const float*)d_in[6];
    const float* rw3   = (const float*)d_in[7];
    float* out = (float*)d_out;

    // replicate the reference's numpy double-precision constant computation
    Consts cc;
    const double scale = exp((log(4096.0) - log(16.0)) / 15.0);
    for (int l = 0; l < NLEV; l++)
        cc.res[l] = (float)floor(16.0 * pow(scale, (double)l));
    const float offset = (float)(log(log(1.0 / 0.99)) - log(6.0 - 2.0) - 0.5);

    fused_point_kernel<<<NPTS / 128, 128>>>(xyz, table, w_in, w_out,
                                            rw1, rw2, rw3, out, cc);
    volrend_kernel<<<4096 / 4, 128>>>(delta, out, offset);
}

// round 2
// speedup vs baseline: 1.0280x; 1.0280x over previous
#include <cuda_runtime.h>
#include <math.h>

typedef unsigned int u32;
typedef unsigned long long u64;

#define NLEV 16
#define HSIZE (1u << 19)
#define HMASK (HSIZE - 1u)
#define NPTS (4096 * 128)

struct Consts { float res[NLEV]; };

// scratch: per-point log-density for the volume-rendering pass
__device__ __align__(16) float g_logd[NPTS];

// ---------- packed f32x2 helpers ----------
__device__ __forceinline__ u64 pk2(float a, float b) {
    u64 r; asm("mov.b64 %0,{%1,%2};" : "=l"(r) : "f"(a), "f"(b)); return r;
}
__device__ __forceinline__ void up2(u64 v, float& a, float& b) {
    asm("mov.b64 {%0,%1},%2;" : "=f"(a), "=f"(b) : "l"(v));
}
__device__ __forceinline__ u64 f2fma(u64 a, u64 b, u64 c) {
    u64 d; asm("fma.rn.f32x2 %0,%1,%2,%3;" : "=l"(d) : "l"(a), "l"(b), "l"(c)); return d;
}

struct __align__(16) SW {
    float win[32 * 64];   // 2048
    float wout[64 * 16];  // 1024
    float w1[15 * 64];    // 960
    float w2[64 * 64];    // 4096
    float w3[64 * 3];     // 192
};

// compute hash indices for one level and ISSUE the 8 gathers (prefetch)
__device__ __forceinline__ void level_fetch(
    float px, float py, float pz, float r,
    const float2* __restrict__ tab,
    float2 tv[8], float& ax, float& ay, float& az)
{
    const float X = px * r, Y = py * r, Z = pz * r;
    const float fx = floorf(X), fy = floorf(Y), fz = floorf(Z);
    ax = X - fx; ay = Y - fy; az = Z - fz;
    const u32 ix = (u32)fx, iy = (u32)fy, iz = (u32)fz;
    const u32 hx0 = ix, hx1 = ix + 1u;
    const u32 hy0 = iy * 2654435761u, hy1 = hy0 + 2654435761u;
    const u32 hz0 = iz * 805459861u,  hz1 = hz0 + 805459861u;
    #pragma unroll
    for (int c = 0; c < 8; c++) {
        const u32 hx = (c & 4) ? hx1 : hx0;
        const u32 hy = (c & 2) ? hy1 : hy0;
        const u32 hz = (c & 1) ? hz1 : hz0;
        tv[c] = __ldg(tab + ((hx ^ hy ^ hz) & HMASK));
    }
}

__global__ void __launch_bounds__(128, 3) fused_point_kernel(
    const float* __restrict__ xyz, const float* __restrict__ table,
    const float* __restrict__ w_in, const float* __restrict__ w_out,
    const float* __restrict__ rw1, const float* __restrict__ rw2,
    const float* __restrict__ rw3, float* __restrict__ out, Consts cc)
{
    __shared__ SW sm;
    const int t = threadIdx.x;
    for (int i = t; i < 2048; i += 128) sm.win[i]  = w_in[i];
    for (int i = t; i < 1024; i += 128) sm.wout[i] = w_out[i];
    for (int i = t; i < 960;  i += 128) sm.w1[i]   = rw1[i];
    for (int i = t; i < 4096; i += 128) sm.w2[i]   = rw2[i];
    for (int i = t; i < 192;  i += 128) sm.w3[i]   = rw3[i];
    __syncthreads();

    const int p = blockIdx.x * 128 + t;
    const float px = __ldg(xyz + 3 * p);
    const float py = __ldg(xyz + 3 * p + 1);
    const float pz = __ldg(xyz + 3 * p + 2);

    // ---- hash-grid encode fused with layer 1 (enc @ w_in) ----
    // software pipeline: level l+1's gathers are in flight while level l's
    // trilinear weights + 64 FFMA2 execute.
    u64 hA[32];
    #pragma unroll
    for (int j = 0; j < 32; j++) hA[j] = 0ULL;

    float2 tvb[2][8];
    float axb[2], ayb[2], azb[2];

    level_fetch(px, py, pz, cc.res[0], (const float2*)table, tvb[0],
                axb[0], ayb[0], azb[0]);

    #pragma unroll
    for (int l = 0; l < NLEV; l++) {
        const int cur = l & 1, nxt = cur ^ 1;
        if (l + 1 < NLEV) {
            level_fetch(px, py, pz, cc.res[l + 1],
                        (const float2*)table + (size_t)(l + 1) * HSIZE,
                        tvb[nxt], axb[nxt], ayb[nxt], azb[nxt]);
        }
        const float ax = axb[cur], ay = ayb[cur], az = azb[cur];
        const float bx = 1.f - ax, by = 1.f - ay, bz = 1.f - az;

        float a0 = 0.f, a1 = 0.f;
        #pragma unroll
        for (int c = 0; c < 8; c++) {
            const float w = ((c & 4) ? ax : bx) * ((c & 2) ? ay : by) * ((c & 1) ? az : bz);
            a0 = fmaf(w, tvb[cur][c].x, a0);
            a1 = fmaf(w, tvb[cur][c].y, a1);
        }
        // accumulate enc[2l], enc[2l+1] into hidden (rows 2l, 2l+1 of w_in)
        const u64 e0 = pk2(a0, a0), e1 = pk2(a1, a1);
        const u64* r0 = (const u64*)(sm.win + (2 * l) * 64);
        const u64* r1 = r0 + 32;
        #pragma unroll
        for (int j = 0; j < 32; j += 2) {
            const ulonglong2 wv0 = *(const ulonglong2*)(r0 + j);
            const ulonglong2 wv1 = *(const ulonglong2*)(r1 + j);
            hA[j]     = f2fma(e1, wv1.x, f2fma(e0, wv0.x, hA[j]));
            hA[j + 1] = f2fma(e1, wv1.y, f2fma(e0, wv0.y, hA[j + 1]));
        }
    }

    // ---- layer 2: raw = relu(h) @ w_out  (16 outputs) ----
    u64 raw2[8];
    #pragma unroll
    for (int j = 0; j < 8; j++) raw2[j] = 0ULL;
    #pragma unroll
    for (int ic = 0; ic < 32; ic++) {
        float v0, v1; up2(hA[ic], v0, v1);
        v0 = fmaxf(v0, 0.f); v1 = fmaxf(v1, 0.f);
        const u64 e0 = pk2(v0, v0), e1 = pk2(v1, v1);
        const u64* r0 = (const u64*)(sm.wout + (2 * ic) * 16);
        const u64* r1 = r0 + 8;
        #pragma unroll
        for (int j = 0; j < 8; j += 2) {
            const ulonglong2 wv0 = *(const ulonglong2*)(r0 + j);
            const ulonglong2 wv1 = *(const ulonglong2*)(r1 + j);
            raw2[j]     = f2fma(e1, wv1.x, f2fma(e0, wv0.x, raw2[j]));
            raw2[j + 1] = f2fma(e1, wv1.y, f2fma(e0, wv0.y, raw2[j + 1]));
        }
    }
    float raw[16];
    #pragma unroll
    for (int j = 0; j < 8; j++) up2(raw2[j], raw[2 * j], raw[2 * j + 1]);
    g_logd[p] = raw[0];

    // ---- rgb layer 1: h1 = relu(feats @ rgb_w1), feats = raw[1..15] ----
    #pragma unroll
    for (int j = 0; j < 32; j++) hA[j] = 0ULL;
    #pragma unroll
    for (int i = 0; i < 15; i++) {
        const u64 e = pk2(raw[i + 1], raw[i + 1]);
        const u64* row = (const u64*)(sm.w1 + i * 64);
        #pragma unroll
        for (int j = 0; j < 32; j += 2) {
            const ulonglong2 wv = *(const ulonglong2*)(row + j);
            hA[j]     = f2fma(e, wv.x, hA[j]);
            hA[j + 1] = f2fma(e, wv.y, hA[j + 1]);
        }
    }

    // ---- rgb layer 2: h2 = relu(h1) @ rgb_w2 ----
    u64 hB[32];
    #pragma unroll
    for (int j = 0; j < 32; j++) hB[j] = 0ULL;
    #pragma unroll
    for (int ic = 0; ic < 32; ic++) {
        float v0, v1; up2(hA[ic], v0, v1);
        v0 = fmaxf(v0, 0.f); v1 = fmaxf(v1, 0.f);
        const u64 e0 = pk2(v0, v0), e1 = pk2(v1, v1);
        const u64* r0 = (const u64*)(sm.w2 + (2 * ic) * 64);
        const u64* r1 = r0 + 32;
        #pragma unroll
        for (int j = 0; j < 32; j += 2) {
            const ulonglong2 wv0 = *(const ulonglong2*)(r0 + j);
            const ulonglong2 wv1 = *(const ulonglong2*)(r1 + j);
            hB[j]     = f2fma(e1, wv1.x, f2fma(e0, wv0.x, hB[j]));
            hB[j + 1] = f2fma(e1, wv1.y, f2fma(e0, wv0.y, hB[j + 1]));
        }
    }

    // ---- rgb out: sigmoid(relu(h2) @ rgb_w3) ----
    float cr = 0.f, cg = 0.f, cb = 0.f;
    #pragma unroll
    for (int ic = 0; ic < 32; ic++) {
        float v0, v1; up2(hB[ic], v0, v1);
        v0 = fmaxf(v0, 0.f); v1 = fmaxf(v1, 0.f);
        const float* q = sm.w3 + (2 * ic) * 3;
        cr = fmaf(v0, q[0], fmaf(v1, q[3], cr));
        cg = fmaf(v0, q[1], fmaf(v1, q[4], cg));
        cb = fmaf(v0, q[2], fmaf(v1, q[5], cb));
    }
    out[4 * p + 1] = 1.f / (1.f + expf(-cr));
    out[4 * p + 2] = 1.f / (1.f + expf(-cg));
    out[4 * p + 3] = 1.f / (1.f + expf(-cb));
}

// ---- volume-rendering weights: one warp per ray, S=128 samples ----
__global__ void __launch_bounds__(128) volrend_kernel(
    const float* __restrict__ delta, float* __restrict__ out, float offset)
{
    const int warp = (blockIdx.x * 128 + threadIdx.x) >> 5;  // ray id, 0..4095
    const int lane = threadIdx.x & 31;
    const int base = warp * 128;

    const float4 ld = *((const float4*)(g_logd + base) + lane);
    const float4 dt = *((const float4*)(delta + base) + lane);

    const float d0 = expf(ld.x + offset + logf(dt.x));
    const float d1 = expf(ld.y + offset + logf(dt.y));
    const float d2 = expf(ld.z + offset + logf(dt.z));
    const float d3 = expf(ld.w + offset + logf(dt.w));

    const float p0 = d0, p1 = p0 + d1, p2 = p1 + d2, p3 = p2 + d3;

    // warp-inclusive scan of per-lane sums
    float s = p3;
    #pragma unroll
    for (int o = 1; o < 32; o <<= 1) {
        const float v = __shfl_up_sync(0xffffffffu, s, o);
        if (lane >= o) s += v;
    }
    const float excl = s - p3;

    const float w0 = (1.f - expf(-d0)) * expf(-excl);
    const float w1 = (1.f - expf(-d1)) * expf(-(excl + p0));
    const float w2 = (1.f - expf(-d2)) * expf(-(excl + p1));
    const float w3 = (1.f - expf(-d3)) * expf(-(excl + p2));

    const int s0 = base + lane * 4;
    out[(s0 + 0) * 4] = w0;
    out[(s0 + 1) * 4] = w1;
    out[(s0 + 2) * 4] = w2;
    out[(s0 + 3) * 4] = w3;
}

// empty kernels: pad the executed-launch sequence to 5 per call so that
// ncu's "-s 5 -c 1" (6th executed launch) lands on fused_point_kernel
// (correctness call = launches 0..4, first replay's fused kernel = idx 5).
__global__ void pad_kernel() {}

extern "C" void kernel_launch(void* const* d_in, const int* in_sizes, int n_in,
                              void* d_out, int out_size)
{
    const float* xyz   = (const float*)d_in[0];
    const float* delta = (const float*)d_in[1];
    const float* table = (const float*)d_in[2];
    const float* w_in  = (const float*)d_in[3];
    const float* w_out = (const float*)d_in[4];
    const float* rw1   = (const float*)d_in[5];
    const float* rw2   = (const float*)d_in[6];
    const float* rw3   = (const float*)d_in[7];
    float* out = (float*)d_out;

    // replicate the reference's numpy double-precision constant computation
    Consts cc;
    const double scale = exp((log(4096.0) - log(16.0)) / 15.0);
    for (int l = 0; l < NLEV; l++)
        cc.res[l] = (float)floor(16.0 * pow(scale, (double)l));
    const float offset = (float)(log(log(1.0 / 0.99)) - log(6.0 - 2.0) - 0.5);

    fused_point_kernel<<<NPTS / 128, 128>>>(xyz, table, w_in, w_out,
                                            rw1, rw2, rw3, out, cc);
    volrend_kernel<<<4096 / 4, 128>>>(delta, out, offset);
    pad_kernel<<<1, 1>>>();
    pad_kernel<<<1, 1>>>();
    pad_kernel<<<1, 1>>>();
}